// round 8
// baseline (speedup 1.0000x reference)
#include <cuda_runtime.h>
#include <math.h>

#define BB 4
#define CC 256
#define KIN 32
#define NN 4096
#define CSPLIT 8

typedef unsigned long long ull;

// ---------------- packed fp32x2 helpers (Blackwell dual-rate fp32) -----------
__device__ __forceinline__ ull pack2(float lo, float hi) {
    ull r; asm("mov.b64 %0, {%1,%2};" : "=l"(r) : "f"(lo), "f"(hi)); return r;
}
__device__ __forceinline__ void unpack2(ull v, float& lo, float& hi) {
    asm("mov.b64 {%0,%1}, %2;" : "=f"(lo), "=f"(hi) : "l"(v));
}
__device__ __forceinline__ void fma2(ull& d, ull a, ull b) {
    asm("fma.rn.f32x2 %0, %1, %2, %0;" : "+l"(d) : "l"(a), "l"(b));
}

// ---------------- scratch (device globals; no allocation allowed) ------------
__device__ float d_fgh[BB][96][NN];                // f(0..31), g(32..63), h(64..95)
__device__ float d_psum2[BB][CSPLIT][NN];          // per-part partial row sums
__device__ float d_inv[BB][NN];                    // 1/rowsum
__device__ float d_opre[CSPLIT][BB][KIN][NN];      // partial o_pre (UNnormalized)

// ---------------- K1: projections f,g,h = W @ x + b --------------------------
__global__ __launch_bounds__(256) void k1_proj(
    const float* __restrict__ x,
    const float* __restrict__ Wf, const float* __restrict__ bf,
    const float* __restrict__ Wg, const float* __restrict__ bg,
    const float* __restrict__ Wh, const float* __restrict__ bh)
{
    int b  = blockIdx.y;
    int n0 = blockIdx.x * 128;
    int tid = threadIdx.x;
    __shared__ float xs[32][128];
    __shared__ float ws[96][36];
    int nt = tid & 31;
    int jt = tid >> 5;

    float acc[12][4];
#pragma unroll
    for (int j = 0; j < 12; j++)
#pragma unroll
        for (int l = 0; l < 4; l++) acc[j][l] = 0.f;

    for (int c0 = 0; c0 < CC; c0 += 32) {
        __syncthreads();
        {
            int n4 = tid & 31, cbase = tid >> 5;
#pragma unroll
            for (int p = 0; p < 4; p++) {
                int cc = cbase + p * 8;
                float4 v = *(const float4*)&x[(((size_t)b * CC) + (c0 + cc)) * NN + n0 + n4 * 4];
                *(float4*)&xs[cc][n4 * 4] = v;
            }
        }
        {
            int c8 = tid & 7, jbase = tid >> 3;
#pragma unroll
            for (int p = 0; p < 3; p++) {
                int j = jbase + p * 32;
                const float* Wp = (j < 32) ? Wf : ((j < 64) ? Wg : Wh);
                int row = j & 31;
                float4 v = *(const float4*)&Wp[row * CC + c0 + c8 * 4];
                ws[j][c8 * 4 + 0] = v.x; ws[j][c8 * 4 + 1] = v.y;
                ws[j][c8 * 4 + 2] = v.z; ws[j][c8 * 4 + 3] = v.w;
            }
        }
        __syncthreads();
#pragma unroll 4
        for (int cc = 0; cc < 32; cc++) {
            float4 xv = *(const float4*)&xs[cc][nt * 4];
#pragma unroll
            for (int jj = 0; jj < 12; jj++) {
                float w = ws[jt * 12 + jj][cc];
                acc[jj][0] += w * xv.x; acc[jj][1] += w * xv.y;
                acc[jj][2] += w * xv.z; acc[jj][3] += w * xv.w;
            }
        }
    }
#pragma unroll
    for (int jj = 0; jj < 12; jj++) {
        int j = jt * 12 + jj;
        float bias = (j < 32) ? bf[j] : ((j < 64) ? bg[j - 32] : bh[j - 64]);
        float4 v;
        v.x = acc[jj][0] + bias; v.y = acc[jj][1] + bias;
        v.z = acc[jj][2] + bias; v.w = acc[jj][3] + bias;
        *(float4*)&d_fgh[b][j][n0 + nt * 4] = v;
    }
}

// ------- K4f2: GEMM + exp, UNNORM attn write from regs, rowsum, PV ----------
// grid: (NN/128 r-tiles, CSPLIT c-parts, BB); block 256
__global__ __launch_bounds__(256) void k4f2(float* __restrict__ attn)
{
    int b    = blockIdx.z;
    int part = blockIdx.y;
    int r0   = blockIdx.x * 128;
    int tid  = threadIdx.x;
    int lane = tid & 31;
    int w    = tid >> 5;

    __shared__ float fs[32][128];       // f tile, resident whole kernel
    __shared__ float gs[32][36];        // g chunk [32k][32c]
    __shared__ float hs[32][36];        // h chunk [32k][32c]
    __shared__ float es[128][36];       // exp tile [128r][32c]

    {   // load f tile [32k][128r]
        int i4 = tid & 31, kb = tid >> 5;
#pragma unroll
        for (int p = 0; p < 4; p++) {
            int k = kb + p * 8;
            *(float4*)&fs[k][i4 * 4] = *(const float4*)&d_fgh[b][k][r0 + i4 * 4];
        }
    }

    int tx = tid & 7, ty = tid >> 3;    // GEMM micro: rows ty*4.., cols tx*4..
    int kl = tid >> 3, c4 = tid & 7;    // g/h loader: k=kl, cols c4*4..

    ull acc[16];
#pragma unroll
    for (int i = 0; i < 16; i++) acc[i] = 0ULL;
    float rs[4] = {0.f, 0.f, 0.f, 0.f};

    float* attn_b = attn + (size_t)b * NN * NN;
    const int CB = NN / CSPLIT;         // 512 cols per block

    for (int it = 0; it < CB / 32; it++) {
        int cc = part * CB + it * 32;
        __syncthreads();   // prev PV readers of es/hs done (also covers fs load)
        *(float4*)&gs[kl][c4 * 4] = *(const float4*)&d_fgh[b][32 + kl][cc + c4 * 4];
        *(float4*)&hs[kl][c4 * 4] = *(const float4*)&d_fgh[b][64 + kl][cc + c4 * 4];
        __syncthreads();

        // GEMM 128x32x32
        ull a2[4][2];
#pragma unroll
        for (int r = 0; r < 4; r++) { a2[r][0] = 0ULL; a2[r][1] = 0ULL; }
#pragma unroll 8
        for (int k = 0; k < 32; k++) {
            float4 fv = *(const float4*)&fs[k][ty * 4];
            const ull* gp = (const ull*)&gs[k][tx * 4];
            ull b0 = gp[0], b1 = gp[1];
            fma2(a2[0][0], pack2(fv.x, fv.x), b0); fma2(a2[0][1], pack2(fv.x, fv.x), b1);
            fma2(a2[1][0], pack2(fv.y, fv.y), b0); fma2(a2[1][1], pack2(fv.y, fv.y), b1);
            fma2(a2[2][0], pack2(fv.z, fv.z), b0); fma2(a2[2][1], pack2(fv.z, fv.z), b1);
            fma2(a2[3][0], pack2(fv.w, fv.w), b0); fma2(a2[3][1], pack2(fv.w, fv.w), b1);
        }

        // exp -> regs; STS to es; rowsum accumulate
        float e[4][4];
#pragma unroll
        for (int r = 0; r < 4; r++) {
            float s0, s1, s2, s3;
            unpack2(a2[r][0], s0, s1);
            unpack2(a2[r][1], s2, s3);
            e[r][0] = __expf(s0); e[r][1] = __expf(s1);
            e[r][2] = __expf(s2); e[r][3] = __expf(s3);
            float4 v = {e[r][0], e[r][1], e[r][2], e[r][3]};
            *(float4*)&es[ty * 4 + r][tx * 4] = v;
            rs[r] += (e[r][0] + e[r][1]) + (e[r][2] + e[r][3]);
        }

        // attn (UNnormalized) straight from regs: col c, rows ty*4..+3 contiguous
#pragma unroll
        for (int q = 0; q < 4; q++) {
            float4 va = {e[0][q], e[1][q], e[2][q], e[3][q]};
            *(float4*)&attn_b[((size_t)(cc + tx * 4 + q)) * NN + r0 + ty * 4] = va;
        }
        __syncthreads();   // es visible

        // PV: lane = k, warp w covers rows w*16..w*16+15, 4-col groups
#pragma unroll 4
        for (int t = 0; t < 8; t++) {
            const ull* hp = (const ull*)&hs[lane][4 * t];
            ull h0 = hp[0], h1 = hp[1];
#pragma unroll
            for (int i = 0; i < 16; i++) {
                const ull* ep = (const ull*)&es[w * 16 + i][4 * t];
                fma2(acc[i], ep[0], h0);
                fma2(acc[i], ep[1], h1);
            }
        }
    }

    // o_pre partials (unnormalized)
#pragma unroll
    for (int i = 0; i < 16; i++) {
        float lo, hi;
        unpack2(acc[i], lo, hi);
        d_opre[part][b][lane][r0 + w * 16 + i] = lo + hi;
    }

    // rowsum partials: reduce over tx (8-lane groups), write from tx==0
#pragma unroll
    for (int r = 0; r < 4; r++) {
#pragma unroll
        for (int off = 1; off < 8; off <<= 1)
            rs[r] += __shfl_xor_sync(0xffffffffu, rs[r], off);
    }
    if (tx == 0) {
#pragma unroll
        for (int r = 0; r < 4; r++)
            d_psum2[b][part][r0 + ty * 4 + r] = rs[r];
    }
}

// ---------------- K3: reduce partials -> 1/sum -------------------------------
__global__ __launch_bounds__(256) void k3_inv()
{
    int b = blockIdx.y;
    int n = blockIdx.x * 256 + threadIdx.x;
    float s = 0.f;
#pragma unroll
    for (int p = 0; p < CSPLIT; p++) s += d_psum2[b][p][n];
    d_inv[b][n] = 1.0f / s;
}

// ---------------- K6: scale attn rows in place by inv[r] ---------------------
// attn[b][c][r] *= inv[b][r]; r contiguous -> fully coalesced
__global__ __launch_bounds__(256) void k6_scale(float* __restrict__ attn)
{
    int b = blockIdx.y;
    int c = blockIdx.x;
    float4* row = (float4*)(attn + (((size_t)b * NN) + c) * NN);
    const float4* iv = (const float4*)d_inv[b];
#pragma unroll
    for (int i = threadIdx.x; i < NN / 4; i += 256) {
        float4 v = row[i];
        float4 s = iv[i];
        v.x *= s.x; v.y *= s.y; v.z *= s.z; v.w *= s.w;
        row[i] = v;
    }
}

// ---------------- K5: y = gamma*(Wv @ (sum(o_parts)*inv) + bv) + x -----------
__global__ __launch_bounds__(256) void k5_out(
    const float* __restrict__ x, const float* __restrict__ Wv,
    const float* __restrict__ bv, const float* __restrict__ gamma,
    float* __restrict__ y)
{
    int b  = blockIdx.y;
    int n0 = blockIdx.x * 128;
    int tid = threadIdx.x;
    __shared__ float os[32][128];
    {
        int n4 = tid & 31, kb = tid >> 5;
#pragma unroll
        for (int p = 0; p < 4; p++) {
            int k = kb + p * 8;
            float4 a = *(const float4*)&d_opre[0][b][k][n0 + n4 * 4];
#pragma unroll
            for (int s = 1; s < CSPLIT; s++) {
                float4 c1 = *(const float4*)&d_opre[s][b][k][n0 + n4 * 4];
                a.x += c1.x; a.y += c1.y; a.z += c1.z; a.w += c1.w;
            }
            *(float4*)&os[k][n4 * 4] = a;
        }
    }
    __syncthreads();
    int n  = tid & 127;
    int cg = tid >> 7;
    float ivn = d_inv[b][n0 + n];
    float ov[32];
#pragma unroll
    for (int k = 0; k < 32; k++) ov[k] = os[k][n] * ivn;
    float gm = gamma[0];

    for (int ci = 0; ci < 128; ci++) {
        int c = cg * 128 + ci;
        float a = bv[c];
        const float4* wv = (const float4*)&Wv[c * 32];
#pragma unroll
        for (int q = 0; q < 8; q++) {
            float4 wq = __ldg(&wv[q]);
            a += wq.x * ov[q * 4 + 0] + wq.y * ov[q * 4 + 1]
               + wq.z * ov[q * 4 + 2] + wq.w * ov[q * 4 + 3];
        }
        size_t idx = (((size_t)b * CC) + c) * NN + n0 + n;
        y[idx] = gm * a + x[idx];
    }
}

// ---------------- launch -----------------------------------------------------
extern "C" void kernel_launch(void* const* d_in, const int* in_sizes, int n_in,
                              void* d_out, int out_size)
{
    (void)in_sizes; (void)n_in; (void)out_size;
    const float* x     = (const float*)d_in[0];
    const float* Wf    = (const float*)d_in[1];
    const float* bf    = (const float*)d_in[2];
    const float* Wg    = (const float*)d_in[3];
    const float* bg    = (const float*)d_in[4];
    const float* Wh    = (const float*)d_in[5];
    const float* bh    = (const float*)d_in[6];
    const float* Wv    = (const float*)d_in[7];
    const float* bv    = (const float*)d_in[8];
    const float* gamma = (const float*)d_in[9];

    float* y    = (float*)d_out;
    float* attn = y + (size_t)BB * CC * NN;

    k1_proj<<<dim3(NN / 128, BB),         256>>>(x, Wf, bf, Wg, bg, Wh, bh);
    k4f2   <<<dim3(NN / 128, CSPLIT, BB), 256>>>(attn);
    k3_inv <<<dim3(NN / 256, BB),         256>>>();
    k6_scale<<<dim3(NN, BB),              256>>>(attn);
    k5_out <<<dim3(NN / 128, BB),         256>>>(x, Wv, bv, gamma, y);
}

// round 11
// speedup vs baseline: 1.0744x; 1.0744x over previous
#include <cuda_runtime.h>
#include <math.h>

#define BB 4
#define CC 256
#define KIN 32
#define NN 4096
#define CSPLIT 8
#define PITCH 34

typedef unsigned long long ull;

// ---------------- packed fp32x2 helpers (Blackwell dual-rate fp32) -----------
__device__ __forceinline__ ull pack2(float lo, float hi) {
    ull r; asm("mov.b64 %0, {%1,%2};" : "=l"(r) : "f"(lo), "f"(hi)); return r;
}
__device__ __forceinline__ void unpack2(ull v, float& lo, float& hi) {
    asm("mov.b64 {%0,%1}, %2;" : "=f"(lo), "=f"(hi) : "l"(v));
}
__device__ __forceinline__ void fma2(ull& d, ull a, ull b) {
    asm("fma.rn.f32x2 %0, %1, %2, %0;" : "+l"(d) : "l"(a), "l"(b));
}
// store float4 as two 8B words (dst must be 8B-aligned)
__device__ __forceinline__ void sts2(float* dst, float4 v) {
    ((ull*)dst)[0] = pack2(v.x, v.y);
    ((ull*)dst)[1] = pack2(v.z, v.w);
}

// ---------------- scratch (device globals; no allocation allowed) ------------
__device__ float d_fgh[BB][96][NN];                // f(0..31), g(32..63), h(64..95)
__device__ float d_psum2[BB][CSPLIT][NN];          // per-part partial row sums
__device__ float d_inv[BB][NN];                    // 1/rowsum
__device__ float d_opre[CSPLIT][BB][KIN][NN];      // partial o_pre (UNnormalized)

// ---------------- K1: projections f,g,h = W @ x + b --------------------------
__global__ __launch_bounds__(256) void k1_proj(
    const float* __restrict__ x,
    const float* __restrict__ Wf, const float* __restrict__ bf,
    const float* __restrict__ Wg, const float* __restrict__ bg,
    const float* __restrict__ Wh, const float* __restrict__ bh)
{
    int b  = blockIdx.y;
    int n0 = blockIdx.x * 128;
    int tid = threadIdx.x;
    __shared__ float xs[32][128];
    __shared__ float ws[96][36];
    int nt = tid & 31;
    int jt = tid >> 5;

    float acc[12][4];
#pragma unroll
    for (int j = 0; j < 12; j++)
#pragma unroll
        for (int l = 0; l < 4; l++) acc[j][l] = 0.f;

    for (int c0 = 0; c0 < CC; c0 += 32) {
        __syncthreads();
        {
            int n4 = tid & 31, cbase = tid >> 5;
#pragma unroll
            for (int p = 0; p < 4; p++) {
                int cc = cbase + p * 8;
                float4 v = *(const float4*)&x[(((size_t)b * CC) + (c0 + cc)) * NN + n0 + n4 * 4];
                *(float4*)&xs[cc][n4 * 4] = v;
            }
        }
        {
            int c8 = tid & 7, jbase = tid >> 3;
#pragma unroll
            for (int p = 0; p < 3; p++) {
                int j = jbase + p * 32;
                const float* Wp = (j < 32) ? Wf : ((j < 64) ? Wg : Wh);
                int row = j & 31;
                float4 v = *(const float4*)&Wp[row * CC + c0 + c8 * 4];
                ws[j][c8 * 4 + 0] = v.x; ws[j][c8 * 4 + 1] = v.y;
                ws[j][c8 * 4 + 2] = v.z; ws[j][c8 * 4 + 3] = v.w;
            }
        }
        __syncthreads();
#pragma unroll 4
        for (int cc = 0; cc < 32; cc++) {
            float4 xv = *(const float4*)&xs[cc][nt * 4];
#pragma unroll
            for (int jj = 0; jj < 12; jj++) {
                float w = ws[jt * 12 + jj][cc];
                acc[jj][0] += w * xv.x; acc[jj][1] += w * xv.y;
                acc[jj][2] += w * xv.z; acc[jj][3] += w * xv.w;
            }
        }
    }
#pragma unroll
    for (int jj = 0; jj < 12; jj++) {
        int j = jt * 12 + jj;
        float bias = (j < 32) ? bf[j] : ((j < 64) ? bg[j - 32] : bh[j - 64]);
        float4 v;
        v.x = acc[jj][0] + bias; v.y = acc[jj][1] + bias;
        v.z = acc[jj][2] + bias; v.w = acc[jj][3] + bias;
        *(float4*)&d_fgh[b][j][n0 + nt * 4] = v;
    }
}

// ------- K4f3: GEMM + exp, unnorm coalesced attn write, rowsum, PV -----------
// grid: (NN/128 r-tiles, CSPLIT c-parts, BB); block 256
__global__ __launch_bounds__(256) void k4f3(float* __restrict__ attn)
{
    int b    = blockIdx.z;
    int part = blockIdx.y;
    int r0   = blockIdx.x * 128;
    int tid  = threadIdx.x;
    int lane = tid & 31;
    int w    = tid >> 5;

    __shared__ float fs[32][128];          // f tile, resident whole kernel
    __shared__ float gs[2][32][PITCH];     // g chunk double-buffered
    __shared__ float hs[2][32][PITCH];     // h chunk double-buffered
    __shared__ float es[128][PITCH];       // exp tile [128r][32c]

    {   // load f tile [32k][128r]
        int i4 = tid & 31, kb = tid >> 5;
#pragma unroll
        for (int p = 0; p < 4; p++) {
            int k = kb + p * 8;
            *(float4*)&fs[k][i4 * 4] = *(const float4*)&d_fgh[b][k][r0 + i4 * 4];
        }
    }

    int tx = tid & 7, ty = tid >> 3;    // GEMM micro: rows ty*4.., cols tx*4..
    int kl = tid >> 3, c4 = tid & 7;    // g/h loader: k=kl, cols c4*4..

    ull acc[16];
#pragma unroll
    for (int i = 0; i < 16; i++) acc[i] = 0ULL;
    float rs[4] = {0.f, 0.f, 0.f, 0.f};

    float* attn_b = attn + (size_t)b * NN * NN;
    const int CB = NN / CSPLIT;         // 512 cols per block
    const int NT = CB / 32;             // 16 tiles

    // preload tile 0 into buffer 0
    {
        int cc = part * CB;
        sts2(&gs[0][kl][c4 * 4], *(const float4*)&d_fgh[b][32 + kl][cc + c4 * 4]);
        sts2(&hs[0][kl][c4 * 4], *(const float4*)&d_fgh[b][64 + kl][cc + c4 * 4]);
    }
    __syncthreads();

    for (int it = 0; it < NT; it++) {
        int cur = it & 1, nxt = cur ^ 1;
        int cc = part * CB + it * 32;

        // prefetch next tile into registers (wrap harmlessly on last iter)
        int cc2 = part * CB + ((it + 1) & (NT - 1)) * 32;
        float4 gv = *(const float4*)&d_fgh[b][32 + kl][cc2 + c4 * 4];
        float4 hv = *(const float4*)&d_fgh[b][64 + kl][cc2 + c4 * 4];

        // GEMM 128x32x32 from gs[cur]
        ull a2[4][2];
#pragma unroll
        for (int r = 0; r < 4; r++) { a2[r][0] = 0ULL; a2[r][1] = 0ULL; }
#pragma unroll 8
        for (int k = 0; k < 32; k++) {
            float4 fv = *(const float4*)&fs[k][ty * 4];
            const ull* gp = (const ull*)&gs[cur][k][tx * 4];
            ull b0 = gp[0], b1 = gp[1];
            fma2(a2[0][0], pack2(fv.x, fv.x), b0); fma2(a2[0][1], pack2(fv.x, fv.x), b1);
            fma2(a2[1][0], pack2(fv.y, fv.y), b0); fma2(a2[1][1], pack2(fv.y, fv.y), b1);
            fma2(a2[2][0], pack2(fv.z, fv.z), b0); fma2(a2[2][1], pack2(fv.z, fv.z), b1);
            fma2(a2[3][0], pack2(fv.w, fv.w), b0); fma2(a2[3][1], pack2(fv.w, fv.w), b1);
        }

        // exp in regs + rowsum accumulate
        float4 ev[4];
#pragma unroll
        for (int r = 0; r < 4; r++) {
            float s0, s1, s2, s3;
            unpack2(a2[r][0], s0, s1);
            unpack2(a2[r][1], s2, s3);
            ev[r].x = __expf(s0); ev[r].y = __expf(s1);
            ev[r].z = __expf(s2); ev[r].w = __expf(s3);
            rs[r] += (ev[r].x + ev[r].y) + (ev[r].z + ev[r].w);
        }

        __syncthreads();   // PV/attn of it-1 done reading es and hs[nxt]
#pragma unroll
        for (int r = 0; r < 4; r++) sts2(&es[ty * 4 + r][tx * 4], ev[r]);
        sts2(&gs[nxt][kl][c4 * 4], gv);
        sts2(&hs[nxt][kl][c4 * 4], hv);
        __syncthreads();   // es (and next g/h) visible

        // attn (UNnormalized): warp w -> cols w*4..w*4+3, rows coalesced
#pragma unroll
        for (int q = 0; q < 4; q++) {
            int c = w * 4 + q;
            size_t ob = ((size_t)(cc + c)) * NN + r0 + lane;
            attn_b[ob]      = es[lane][c];
            attn_b[ob + 32] = es[lane + 32][c];
            attn_b[ob + 64] = es[lane + 64][c];
            attn_b[ob + 96] = es[lane + 96][c];
        }

        // PV: lane = k, warp w covers rows w*16..w*16+15, 4-col groups
#pragma unroll 4
        for (int t = 0; t < 8; t++) {
            const ull* hp = (const ull*)&hs[cur][lane][4 * t];
            ull h0 = hp[0], h1 = hp[1];
#pragma unroll
            for (int i = 0; i < 16; i++) {
                const ull* ep = (const ull*)&es[w * 16 + i][4 * t];
                fma2(acc[i], ep[0], h0);
                fma2(acc[i], ep[1], h1);
            }
        }
    }

    // o_pre partials (unnormalized)
#pragma unroll
    for (int i = 0; i < 16; i++) {
        float lo, hi;
        unpack2(acc[i], lo, hi);
        d_opre[part][b][lane][r0 + w * 16 + i] = lo + hi;
    }

    // rowsum partials: reduce over tx (8-lane groups), write from tx==0
#pragma unroll
    for (int r = 0; r < 4; r++) {
#pragma unroll
        for (int off = 1; off < 8; off <<= 1)
            rs[r] += __shfl_xor_sync(0xffffffffu, rs[r], off);
    }
    if (tx == 0) {
#pragma unroll
        for (int r = 0; r < 4; r++)
            d_psum2[b][part][r0 + ty * 4 + r] = rs[r];
    }
}

// ---------------- K3: reduce partials -> 1/sum -------------------------------
__global__ __launch_bounds__(256) void k3_inv()
{
    int b = blockIdx.y;
    int n = blockIdx.x * 256 + threadIdx.x;
    float s = 0.f;
#pragma unroll
    for (int p = 0; p < CSPLIT; p++) s += d_psum2[b][p][n];
    d_inv[b][n] = 1.0f / s;
}

// ---------------- K6: scale attn rows in place by inv[r] ---------------------
__global__ __launch_bounds__(256) void k6_scale(float* __restrict__ attn)
{
    int b = blockIdx.y;
    int c = blockIdx.x;
    float4* row = (float4*)(attn + (((size_t)b * NN) + c) * NN);
    const float4* iv = (const float4*)d_inv[b];
#pragma unroll
    for (int i = threadIdx.x; i < NN / 4; i += 256) {
        float4 v = row[i];
        float4 s = iv[i];
        v.x *= s.x; v.y *= s.y; v.z *= s.z; v.w *= s.w;
        row[i] = v;
    }
}

// ---------------- K5: y = gamma*(Wv @ (sum(o_parts)*inv) + bv) + x -----------
__global__ __launch_bounds__(256) void k5_out(
    const float* __restrict__ x, const float* __restrict__ Wv,
    const float* __restrict__ bv, const float* __restrict__ gamma,
    float* __restrict__ y)
{
    int b  = blockIdx.y;
    int n0 = blockIdx.x * 128;
    int tid = threadIdx.x;
    __shared__ float os[32][128];
    {
        int n4 = tid & 31, kb = tid >> 5;
#pragma unroll
        for (int p = 0; p < 4; p++) {
            int k = kb + p * 8;
            float4 a = *(const float4*)&d_opre[0][b][k][n0 + n4 * 4];
#pragma unroll
            for (int s = 1; s < CSPLIT; s++) {
                float4 c1 = *(const float4*)&d_opre[s][b][k][n0 + n4 * 4];
                a.x += c1.x; a.y += c1.y; a.z += c1.z; a.w += c1.w;
            }
            *(float4*)&os[k][n4 * 4] = a;
        }
    }
    __syncthreads();
    int n  = tid & 127;
    int cg = tid >> 7;
    float ivn = d_inv[b][n0 + n];
    float ov[32];
#pragma unroll
    for (int k = 0; k < 32; k++) ov[k] = os[k][n] * ivn;
    float gm = gamma[0];

    for (int ci = 0; ci < 128; ci++) {
        int c = cg * 128 + ci;
        float a = bv[c];
        const float4* wv = (const float4*)&Wv[c * 32];
#pragma unroll
        for (int q = 0; q < 8; q++) {
            float4 wq = __ldg(&wv[q]);
            a += wq.x * ov[q * 4 + 0] + wq.y * ov[q * 4 + 1]
               + wq.z * ov[q * 4 + 2] + wq.w * ov[q * 4 + 3];
        }
        size_t idx = (((size_t)b * CC) + c) * NN + n0 + n;
        y[idx] = gm * a + x[idx];
    }
}

// ---------------- launch -----------------------------------------------------
extern "C" void kernel_launch(void* const* d_in, const int* in_sizes, int n_in,
                              void* d_out, int out_size)
{
    (void)in_sizes; (void)n_in; (void)out_size;
    const float* x     = (const float*)d_in[0];
    const float* Wf    = (const float*)d_in[1];
    const float* bf    = (const float*)d_in[2];
    const float* Wg    = (const float*)d_in[3];
    const float* bg    = (const float*)d_in[4];
    const float* Wh    = (const float*)d_in[5];
    const float* bh    = (const float*)d_in[6];
    const float* Wv    = (const float*)d_in[7];
    const float* bv    = (const float*)d_in[8];
    const float* gamma = (const float*)d_in[9];

    float* y    = (float*)d_out;
    float* attn = y + (size_t)BB * CC * NN;

    k1_proj <<<dim3(NN / 128, BB),         256>>>(x, Wf, bf, Wg, bg, Wh, bh);
    k4f3    <<<dim3(NN / 128, CSPLIT, BB), 256>>>(attn);
    k3_inv  <<<dim3(NN / 256, BB),         256>>>();
    k6_scale<<<dim3(NN, BB),               256>>>(attn);
    k5_out  <<<dim3(NN / 128, BB),         256>>>(x, Wv, bv, gamma, y);
}

// round 14
// speedup vs baseline: 1.0909x; 1.0154x over previous
#include <cuda_runtime.h>
#include <math.h>

#define BB 4
#define CC 256
#define KIN 32
#define NN 4096
#define CSPLIT 8
#define EPITCH 36
#define HPITCH 33

typedef unsigned long long ull;

// ---------------- packed fp32x2 helpers (Blackwell dual-rate fp32) -----------
__device__ __forceinline__ ull pack2(float lo, float hi) {
    ull r; asm("mov.b64 %0, {%1,%2};" : "=l"(r) : "f"(lo), "f"(hi)); return r;
}
__device__ __forceinline__ void unpack2(ull v, float& lo, float& hi) {
    asm("mov.b64 {%0,%1}, %2;" : "=f"(lo), "=f"(hi) : "l"(v));
}
__device__ __forceinline__ void fma2(ull& d, ull a, ull b) {
    asm("fma.rn.f32x2 %0, %1, %2, %0;" : "+l"(d) : "l"(a), "l"(b));
}

// ---------------- scratch (device globals; no allocation allowed) ------------
__device__ float d_fgh[BB][96][NN];                // f(0..31), g(32..63), h(64..95)
__device__ float d_psum2[BB][CSPLIT][NN];          // per-part partial row sums
__device__ float d_inv[BB][NN];                    // 1/rowsum
__device__ float d_opre[CSPLIT][BB][KIN][NN];      // partial o_pre (UNnormalized)

// ---------------- K1: projections f,g,h = W @ x + b --------------------------
__global__ __launch_bounds__(256) void k1_proj(
    const float* __restrict__ x,
    const float* __restrict__ Wf, const float* __restrict__ bf,
    const float* __restrict__ Wg, const float* __restrict__ bg,
    const float* __restrict__ Wh, const float* __restrict__ bh)
{
    int b  = blockIdx.y;
    int n0 = blockIdx.x * 128;
    int tid = threadIdx.x;
    __shared__ float xs[32][128];
    __shared__ float ws[96][36];
    int nt = tid & 31;
    int jt = tid >> 5;

    float acc[12][4];
#pragma unroll
    for (int j = 0; j < 12; j++)
#pragma unroll
        for (int l = 0; l < 4; l++) acc[j][l] = 0.f;

    for (int c0 = 0; c0 < CC; c0 += 32) {
        __syncthreads();
        {
            int n4 = tid & 31, cbase = tid >> 5;
#pragma unroll
            for (int p = 0; p < 4; p++) {
                int cc = cbase + p * 8;
                float4 v = *(const float4*)&x[(((size_t)b * CC) + (c0 + cc)) * NN + n0 + n4 * 4];
                *(float4*)&xs[cc][n4 * 4] = v;
            }
        }
        {
            int c8 = tid & 7, jbase = tid >> 3;
#pragma unroll
            for (int p = 0; p < 3; p++) {
                int j = jbase + p * 32;
                const float* Wp = (j < 32) ? Wf : ((j < 64) ? Wg : Wh);
                int row = j & 31;
                float4 v = *(const float4*)&Wp[row * CC + c0 + c8 * 4];
                ws[j][c8 * 4 + 0] = v.x; ws[j][c8 * 4 + 1] = v.y;
                ws[j][c8 * 4 + 2] = v.z; ws[j][c8 * 4 + 3] = v.w;
            }
        }
        __syncthreads();
#pragma unroll 4
        for (int cc = 0; cc < 32; cc++) {
            float4 xv = *(const float4*)&xs[cc][nt * 4];
#pragma unroll
            for (int jj = 0; jj < 12; jj++) {
                float w = ws[jt * 12 + jj][cc];
                acc[jj][0] += w * xv.x; acc[jj][1] += w * xv.y;
                acc[jj][2] += w * xv.z; acc[jj][3] += w * xv.w;
            }
        }
    }
#pragma unroll
    for (int jj = 0; jj < 12; jj++) {
        int j = jt * 12 + jj;
        float bias = (j < 32) ? bf[j] : ((j < 64) ? bg[j - 32] : bh[j - 64]);
        float4 v;
        v.x = acc[jj][0] + bias; v.y = acc[jj][1] + bias;
        v.z = acc[jj][2] + bias; v.w = acc[jj][3] + bias;
        *(float4*)&d_fgh[b][j][n0 + nt * 4] = v;
    }
}

// ------- K4f4: GEMM + exp, unnorm coalesced attn write, rowsum, PV -----------
// grid: (NN/128 r-tiles, CSPLIT c-parts, BB); block 256
__global__ __launch_bounds__(256, 3) void k4f4(float* __restrict__ attn)
{
    int b    = blockIdx.z;
    int part = blockIdx.y;
    int r0   = blockIdx.x * 128;
    int tid  = threadIdx.x;
    int lane = tid & 31;
    int w    = tid >> 5;

    __shared__ float fs[32][128];             // f tile, resident whole kernel
    __shared__ float gs[2][32][EPITCH];       // g chunk [k][c], double-buffered
    __shared__ float hs_t[2][32][HPITCH];     // h chunk TRANSPOSED [c][k]
    __shared__ float es[128][EPITCH];         // exp tile [128r][32c]

    {   // load f tile [32k][128r]
        int i4 = tid & 31, kb = tid >> 5;
#pragma unroll
        for (int p = 0; p < 4; p++) {
            int k = kb + p * 8;
            *(float4*)&fs[k][i4 * 4] = *(const float4*)&d_fgh[b][k][r0 + i4 * 4];
        }
    }

    int tx = tid & 7, ty = tid >> 3;    // GEMM micro: rows ty*4.., cols tx*4..
    int kl = tid >> 3, c4 = tid & 7;    // g/h loader: k=kl, cols c4*4..

    ull acc[16];
#pragma unroll
    for (int i = 0; i < 16; i++) acc[i] = 0ULL;
    float rs[4] = {0.f, 0.f, 0.f, 0.f};

    float* attn_b = attn + (size_t)b * NN * NN;
    const int CB = NN / CSPLIT;         // 512 cols per block
    const int NT = CB / 32;             // 16 tiles

    // preload tile 0 into buffer 0
    {
        int cc = part * CB;
        float4 gv = *(const float4*)&d_fgh[b][32 + kl][cc + c4 * 4];
        float4 hv = *(const float4*)&d_fgh[b][64 + kl][cc + c4 * 4];
        *(float4*)&gs[0][kl][c4 * 4] = gv;
        hs_t[0][c4 * 4 + 0][kl] = hv.x;
        hs_t[0][c4 * 4 + 1][kl] = hv.y;
        hs_t[0][c4 * 4 + 2][kl] = hv.z;
        hs_t[0][c4 * 4 + 3][kl] = hv.w;
    }
    __syncthreads();

    for (int it = 0; it < NT; it++) {
        int cur = it & 1, nxt = cur ^ 1;
        int cc = part * CB + it * 32;

        // prefetch next tile into registers (wrap harmlessly on last iter)
        int cc2 = part * CB + ((it + 1) & (NT - 1)) * 32;
        float4 gv = *(const float4*)&d_fgh[b][32 + kl][cc2 + c4 * 4];
        float4 hv = *(const float4*)&d_fgh[b][64 + kl][cc2 + c4 * 4];

        // GEMM 128x32x32 from gs[cur] (LDS.128 operands)
        ull a2[4][2];
#pragma unroll
        for (int r = 0; r < 4; r++) { a2[r][0] = 0ULL; a2[r][1] = 0ULL; }
#pragma unroll 8
        for (int k = 0; k < 32; k++) {
            float4 fv = *(const float4*)&fs[k][ty * 4];
            float4 gq = *(const float4*)&gs[cur][k][tx * 4];
            ull b0 = ((const ull*)&gq)[0], b1 = ((const ull*)&gq)[1];
            fma2(a2[0][0], pack2(fv.x, fv.x), b0); fma2(a2[0][1], pack2(fv.x, fv.x), b1);
            fma2(a2[1][0], pack2(fv.y, fv.y), b0); fma2(a2[1][1], pack2(fv.y, fv.y), b1);
            fma2(a2[2][0], pack2(fv.z, fv.z), b0); fma2(a2[2][1], pack2(fv.z, fv.z), b1);
            fma2(a2[3][0], pack2(fv.w, fv.w), b0); fma2(a2[3][1], pack2(fv.w, fv.w), b1);
        }

        // exp in regs + rowsum accumulate
        float4 ev[4];
#pragma unroll
        for (int r = 0; r < 4; r++) {
            float s0, s1, s2, s3;
            unpack2(a2[r][0], s0, s1);
            unpack2(a2[r][1], s2, s3);
            ev[r].x = __expf(s0); ev[r].y = __expf(s1);
            ev[r].z = __expf(s2); ev[r].w = __expf(s3);
            rs[r] += (ev[r].x + ev[r].y) + (ev[r].z + ev[r].w);
        }

        __syncthreads();   // PV/attn of it-1 done reading es and hs_t[nxt]/gs[nxt]
#pragma unroll
        for (int r = 0; r < 4; r++)
            *(float4*)&es[ty * 4 + r][tx * 4] = ev[r];
        *(float4*)&gs[nxt][kl][c4 * 4] = gv;
        hs_t[nxt][c4 * 4 + 0][kl] = hv.x;
        hs_t[nxt][c4 * 4 + 1][kl] = hv.y;
        hs_t[nxt][c4 * 4 + 2][kl] = hv.z;
        hs_t[nxt][c4 * 4 + 3][kl] = hv.w;
        __syncthreads();   // es (and next g/h) visible

        // attn (UNnormalized): warp w -> cols w*4..w*4+3, rows coalesced
#pragma unroll
        for (int q = 0; q < 4; q++) {
            int c = w * 4 + q;
            size_t ob = ((size_t)(cc + c)) * NN + r0 + lane;
            attn_b[ob]      = es[lane][c];
            attn_b[ob + 32] = es[lane + 32][c];
            attn_b[ob + 64] = es[lane + 64][c];
            attn_b[ob + 96] = es[lane + 96][c];
        }

        // PV: lane = k, warp w covers rows w*16..w*16+15, 4-col groups
#pragma unroll 4
        for (int t = 0; t < 8; t++) {
            ull h0 = pack2(hs_t[cur][4 * t + 0][lane], hs_t[cur][4 * t + 1][lane]);
            ull h1 = pack2(hs_t[cur][4 * t + 2][lane], hs_t[cur][4 * t + 3][lane]);
#pragma unroll
            for (int i = 0; i < 16; i++) {
                float4 eq = *(const float4*)&es[w * 16 + i][4 * t];
                fma2(acc[i], ((const ull*)&eq)[0], h0);
                fma2(acc[i], ((const ull*)&eq)[1], h1);
            }
        }
    }

    // o_pre partials (unnormalized)
#pragma unroll
    for (int i = 0; i < 16; i++) {
        float lo, hi;
        unpack2(acc[i], lo, hi);
        d_opre[part][b][lane][r0 + w * 16 + i] = lo + hi;
    }

    // rowsum partials: reduce over tx (8-lane groups), write from tx==0
#pragma unroll
    for (int r = 0; r < 4; r++) {
#pragma unroll
        for (int off = 1; off < 8; off <<= 1)
            rs[r] += __shfl_xor_sync(0xffffffffu, rs[r], off);
    }
    if (tx == 0) {
#pragma unroll
        for (int r = 0; r < 4; r++)
            d_psum2[b][part][r0 + ty * 4 + r] = rs[r];
    }
}

// ---------------- K3: reduce partials -> 1/sum -------------------------------
__global__ __launch_bounds__(256) void k3_inv()
{
    int b = blockIdx.y;
    int n = blockIdx.x * 256 + threadIdx.x;
    float s = 0.f;
#pragma unroll
    for (int p = 0; p < CSPLIT; p++) s += d_psum2[b][p][n];
    d_inv[b][n] = 1.0f / s;
}

// ---------------- K6: scale attn rows in place by inv[r] ---------------------
__global__ __launch_bounds__(256) void k6_scale(float* __restrict__ attn)
{
    int b = blockIdx.y;
    int c = blockIdx.x;
    float4* row = (float4*)(attn + (((size_t)b * NN) + c) * NN);
    const float4* iv = (const float4*)d_inv[b];
#pragma unroll
    for (int i = threadIdx.x; i < NN / 4; i += 256) {
        float4 v = row[i];
        float4 s = iv[i];
        v.x *= s.x; v.y *= s.y; v.z *= s.z; v.w *= s.w;
        row[i] = v;
    }
}

// ---------------- K5: y = gamma*(Wv @ (sum(o_parts)*inv) + bv) + x -----------
__global__ __launch_bounds__(256) void k5_out(
    const float* __restrict__ x, const float* __restrict__ Wv,
    const float* __restrict__ bv, const float* __restrict__ gamma,
    float* __restrict__ y)
{
    int b  = blockIdx.y;
    int n0 = blockIdx.x * 128;
    int tid = threadIdx.x;
    __shared__ float os[32][128];
    {
        int n4 = tid & 31, kb = tid >> 5;
#pragma unroll
        for (int p = 0; p < 4; p++) {
            int k = kb + p * 8;
            float4 a = *(const float4*)&d_opre[0][b][k][n0 + n4 * 4];
#pragma unroll
            for (int s = 1; s < CSPLIT; s++) {
                float4 c1 = *(const float4*)&d_opre[s][b][k][n0 + n4 * 4];
                a.x += c1.x; a.y += c1.y; a.z += c1.z; a.w += c1.w;
            }
            *(float4*)&os[k][n4 * 4] = a;
        }
    }
    __syncthreads();
    int n  = tid & 127;
    int cg = tid >> 7;
    float ivn = d_inv[b][n0 + n];
    float ov[32];
#pragma unroll
    for (int k = 0; k < 32; k++) ov[k] = os[k][n] * ivn;
    float gm = gamma[0];

    for (int ci = 0; ci < 128; ci++) {
        int c = cg * 128 + ci;
        float a = bv[c];
        const float4* wv = (const float4*)&Wv[c * 32];
#pragma unroll
        for (int q = 0; q < 8; q++) {
            float4 wq = __ldg(&wv[q]);
            a += wq.x * ov[q * 4 + 0] + wq.y * ov[q * 4 + 1]
               + wq.z * ov[q * 4 + 2] + wq.w * ov[q * 4 + 3];
        }
        size_t idx = (((size_t)b * CC) + c) * NN + n0 + n;
        y[idx] = gm * a + x[idx];
    }
}

// ---------------- launch -----------------------------------------------------
extern "C" void kernel_launch(void* const* d_in, const int* in_sizes, int n_in,
                              void* d_out, int out_size)
{
    (void)in_sizes; (void)n_in; (void)out_size;
    const float* x     = (const float*)d_in[0];
    const float* Wf    = (const float*)d_in[1];
    const float* bf    = (const float*)d_in[2];
    const float* Wg    = (const float*)d_in[3];
    const float* bg    = (const float*)d_in[4];
    const float* Wh    = (const float*)d_in[5];
    const float* bh    = (const float*)d_in[6];
    const float* Wv    = (const float*)d_in[7];
    const float* bv    = (const float*)d_in[8];
    const float* gamma = (const float*)d_in[9];

    float* y    = (float*)d_out;
    float* attn = y + (size_t)BB * CC * NN;

    k1_proj <<<dim3(NN / 128, BB),         256>>>(x, Wf, bf, Wg, bg, Wh, bh);
    k4f4    <<<dim3(NN / 128, CSPLIT, BB), 256>>>(attn);
    k3_inv  <<<dim3(NN / 256, BB),         256>>>();
    k6_scale<<<dim3(NN, BB),               256>>>(attn);
    k5_out  <<<dim3(NN / 128, BB),         256>>>(x, Wv, bv, gamma, y);
}